// round 7
// baseline (speedup 1.0000x reference)
#include <cuda_runtime.h>
#include <math.h>
#include <stddef.h>

#define N_EDGES   1000000
#define FEA       64
#define NC        256
#define NEPB      64
#define EPSV      1e-5f
#define INV_SQRT2 0.70710678118654752f

typedef unsigned long long ull;

// packed fp32x2 FMA (SASS FFMA2) — exact fp32 per lane, 2x FMA throughput
#define FMA2(d, a, b, c) \
    asm("fma.rn.f32x2 %0, %1, %2, %3;" : "=l"(d) : "l"(a), "l"(b), "l"(c))

__device__ __forceinline__ float2 u2f2(ull v) {
    float2 r;
    asm("mov.b64 {%0, %1}, %2;" : "=f"(r.x), "=f"(r.y) : "l"(v));
    return r;
}
__device__ __forceinline__ ull f22u(float lo, float hi) {
    ull r;
    asm("mov.b64 %0, {%1, %2};" : "=l"(r) : "f"(lo), "f"(hi));
    return r;
}

// ---------------- scratch ----------------
__device__ float g_gated[(size_t)N_EDGES * 128];
__device__ float g_nbr[(size_t)N_EDGES * 64];
__device__ float g_sum1[NC * 128];
__device__ float g_sq1 [NC * 128];
__device__ float g_sum2[NC * 64];
__device__ float g_sq2 [NC * 64];
__device__ float g_cnt [NC];
__device__ float g_mean1[NC * 128];
__device__ float g_inv1 [NC * 128];
__device__ float g_mean2[NC * 64];
__device__ float g_inv2 [NC * 64];

// ---------------- kernel 0: zero stats ----------------
__global__ void k_zero() {
    int i = blockIdx.x * blockDim.x + threadIdx.x;
    if (i < NC * 128) { g_sum1[i] = 0.f; g_sq1[i] = 0.f; }
    if (i < NC * 64)  { g_sum2[i] = 0.f; g_sq2[i] = 0.f; }
    if (i < NC)       { g_cnt[i] = 0.f; }
}

// ---------------- kernel 1: gather + GEMM (f32x2 k-paired) + stats1 ----------------
// dyn smem (floats): sA[64][132] | sWT[128][130] (= ull[128][65]) | redS[1024] | redQ[1024]
#define K1_SA    (64 * 132)
#define K1_SWT   (128 * 130)
#define K1_RED   1024
#define K1_SMEM  ((K1_SA + K1_SWT + 2 * K1_RED) * 4)

__global__ __launch_bounds__(256) void k_gemm_stats(
    const float* __restrict__ atom, const float* __restrict__ edge,
    const int* __restrict__ nbr, const int* __restrict__ ce,
    const float* __restrict__ Wfull)
{
    extern __shared__ float sm[];
    float* sA   = sm;                      // [e][k], row stride 132
    float* sWT  = sm + K1_SA;              // transposed W: [j][k], row stride 130 (65 ull, odd -> conflict-free)
    float* redS = sWT + K1_SWT;
    float* redQ = redS + K1_RED;
    __shared__ int sC[NEPB];

    const int tid = threadIdx.x;
    const int e0  = blockIdx.x * NEPB;

    // load W_full transposed: sWT[j][k] = W[k][j]
    for (int idx = tid; idx < 128 * 128; idx += 256) {
        int k = idx >> 7, j = idx & 127;
        sWT[j * 130 + k] = Wfull[idx];
    }

    // load total = [diff | edge] tile
    {
        const int e_l  = tid >> 2;
        const int quad = tid & 3;
        const int eg   = e0 + e_l;
        if (quad == 0) sC[e_l] = ce[eg];
        const int i0 = nbr[2 * eg + 0];
        const int i1 = nbr[2 * eg + 1];
#pragma unroll
        for (int m = 0; m < 4; m++) {
            int k = quad * 16 + m * 4;
            float4 a1 = *(const float4*)(atom + (size_t)i1 * FEA + k);
            float4 a0 = *(const float4*)(atom + (size_t)i0 * FEA + k);
            float4 d;
            d.x = a1.x - a0.x; d.y = a1.y - a0.y; d.z = a1.z - a0.z; d.w = a1.w - a0.w;
            *(float4*)(sA + e_l * 132 + k) = d;
            float4 ev = *(const float4*)(edge + (size_t)eg * FEA + k);
            *(float4*)(sA + e_l * 132 + 64 + k) = ev;
        }
    }
    __syncthreads();

    // GEMM: thread (terow, tcol) computes 8 edges x cols {tcol, tcol+32, tcol+64, tcol+96}
    // k-paired f32x2 accumulators: acc = (sum over even k, sum over odd k)
    const int tcol  = tid & 31;
    const int terow = tid >> 5;

    ull acc[8][4];
#pragma unroll
    for (int i = 0; i < 8; i++)
#pragma unroll
        for (int m = 0; m < 4; m++) acc[i][m] = 0ull;

    const ull* aBase = (const ull*)sA + (size_t)(terow * 8) * 66;   // 132 floats = 66 ull per edge
    const ull* bW    = (const ull*)sWT;                              // 65 ull per j-row
    const ull* b0 = bW + (size_t)tcol * 65;
    const ull* b1 = b0 + (size_t)32 * 65;
    const ull* b2 = b0 + (size_t)64 * 65;
    const ull* b3 = b0 + (size_t)96 * 65;

#pragma unroll 4
    for (int kp = 0; kp < 64; kp++) {
        ull w0 = b0[kp], w1 = b1[kp], w2 = b2[kp], w3 = b3[kp];
#pragma unroll
        for (int i = 0; i < 8; i++) {
            ull a = aBase[i * 66 + kp];   // warp-broadcast LDS64
            FMA2(acc[i][0], a, w0, acc[i][0]);
            FMA2(acc[i][1], a, w1, acc[i][1]);
            FMA2(acc[i][2], a, w2, acc[i][2]);
            FMA2(acc[i][3], a, w3, acc[i][3]);
        }
    }

    // finalize (lo+hi), write gated, compute stats
    float v[8][4];
#pragma unroll
    for (int i = 0; i < 8; i++) {
#pragma unroll
        for (int m = 0; m < 4; m++) {
            float2 p = u2f2(acc[i][m]);
            v[i][m] = p.x + p.y;
        }
        size_t e = (size_t)(e0 + terow * 8 + i);
#pragma unroll
        for (int m = 0; m < 4; m++)
            g_gated[e * 128 + tcol + 32 * m] = v[i][m];
    }

    const int cF = sC[0], cL = sC[NEPB - 1];
    if (cF == cL) {
        float s[4] = {0,0,0,0}, q[4] = {0,0,0,0};
#pragma unroll
        for (int i = 0; i < 8; i++)
#pragma unroll
            for (int m = 0; m < 4; m++) { float x = v[i][m]; s[m] += x; q[m] += x * x; }
#pragma unroll
        for (int m = 0; m < 4; m++) {
            redS[terow * 128 + tcol + 32 * m] = s[m];
            redQ[terow * 128 + tcol + 32 * m] = q[m];
        }
        __syncthreads();
        if (tid < 128) {
            float S = 0.f, Q = 0.f;
#pragma unroll
            for (int r = 0; r < 8; r++) { S += redS[r * 128 + tid]; Q += redQ[r * 128 + tid]; }
            atomicAdd(&g_sum1[cF * 128 + tid], S);
            atomicAdd(&g_sq1 [cF * 128 + tid], Q);
        }
    } else {
        int cc = sC[terow * 8];
        float s[4] = {0,0,0,0}, q[4] = {0,0,0,0};
#pragma unroll
        for (int i = 0; i < 8; i++) {
            int ci = sC[terow * 8 + i];
            if (ci != cc) {
#pragma unroll
                for (int m = 0; m < 4; m++) {
                    int base = cc * 128 + tcol + 32 * m;
                    atomicAdd(&g_sum1[base], s[m]);
                    atomicAdd(&g_sq1 [base], q[m]);
                    s[m] = 0.f; q[m] = 0.f;
                }
                cc = ci;
            }
#pragma unroll
            for (int m = 0; m < 4; m++) { float x = v[i][m]; s[m] += x; q[m] += x * x; }
        }
#pragma unroll
        for (int m = 0; m < 4; m++) {
            int base = cc * 128 + tcol + 32 * m;
            atomicAdd(&g_sum1[base], s[m]);
            atomicAdd(&g_sq1 [base], q[m]);
        }
    }

    if (tid == 0) {
        int cc = sC[0]; float run = 0.f;
        for (int i = 0; i < NEPB; i++) {
            if (sC[i] != cc) { atomicAdd(&g_cnt[cc], run); cc = sC[i]; run = 0.f; }
            run += 1.f;
        }
        atomicAdd(&g_cnt[cc], run);
    }
}

// ---------------- kernel 2/4: finalize stats ----------------
__global__ void k_fin1() {
    int i = blockIdx.x * blockDim.x + threadIdx.x;
    if (i >= NC * 128) return;
    float cnt = fmaxf(g_cnt[i >> 7], 1.f);
    float mean = g_sum1[i] / cnt;
    float var  = g_sq1[i] / cnt - mean * mean;
    g_mean1[i] = mean;
    g_inv1[i]  = rsqrtf(var + EPSV);
}
__global__ void k_fin2() {
    int i = blockIdx.x * blockDim.x + threadIdx.x;
    if (i >= NC * 64) return;
    float cnt = fmaxf(g_cnt[i >> 6], 1.f);
    float mean = g_sum2[i] / cnt;
    float var  = g_sq2[i] / cnt - mean * mean;
    g_mean2[i] = mean;
    g_inv2[i]  = rsqrtf(var + EPSV);
}

// ---------------- kernel 3: norm1 + gate/filter + stats2 (memory-bound, unchanged) ----------------
__global__ __launch_bounds__(256) void k_gate_stats(
    const int* __restrict__ ce, const float* __restrict__ Wmask,
    const float* __restrict__ gamma1, const float* __restrict__ beta1)
{
    __shared__ int   sC[NEPB];
    __shared__ float redS[8 * 64], redQ[8 * 64];
    const int tid = threadIdx.x, l = tid & 31, w = tid >> 5;
    const int e0 = blockIdx.x * NEPB;
    if (tid < NEPB) sC[tid] = ce[e0 + tid];
    __syncthreads();

    const float ga0 = gamma1[l],      be0 = beta1[l];
    const float ga1 = gamma1[l + 32], be1 = beta1[l + 32];
    const float ga2 = gamma1[l + 64], be2 = beta1[l + 64];
    const float ga3 = gamma1[l + 96], be3 = beta1[l + 96];
    const float wm0 = Wmask[l], wm1 = Wmask[l + 32];

    const bool uniform = (sC[0] == sC[NEPB - 1]);
    float s0 = 0.f, q0 = 0.f, s1 = 0.f, q1 = 0.f;
    int cc = sC[w * 8];
#pragma unroll
    for (int i = 0; i < 8; i++) {
        const int e = e0 + w * 8 + i;
        const int c = sC[w * 8 + i];
        const float* gp = g_gated + (size_t)e * 128;
        float x0 = gp[l], x1 = gp[l + 32], x2 = gp[l + 64], x3 = gp[l + 96];
        const float* mp = g_mean1 + c * 128;
        const float* ip = g_inv1  + c * 128;
        x0 = (x0 - mp[l])      * ip[l]      * ga0 + be0;
        x1 = (x1 - mp[l + 32]) * ip[l + 32] * ga1 + be1;
        x2 = (x2 - mp[l + 64]) * ip[l + 64] * ga2 + be2;
        x3 = (x3 - mp[l + 96]) * ip[l + 96] * ga3 + be3;
        float vv = x2 * wm0 + x3 * wm1;
#pragma unroll
        for (int off = 16; off; off >>= 1) vv += __shfl_xor_sync(0xFFFFFFFFu, vv, off);
        float f = tanhf(vv);
        float n0 = f * fmaxf(x0, 0.f);
        float n1 = f * fmaxf(x1, 0.f);
        g_nbr[(size_t)e * 64 + l]      = n0;
        g_nbr[(size_t)e * 64 + l + 32] = n1;
        if (!uniform && c != cc) {
            atomicAdd(&g_sum2[cc * 64 + l], s0);      atomicAdd(&g_sq2[cc * 64 + l], q0);
            atomicAdd(&g_sum2[cc * 64 + l + 32], s1); atomicAdd(&g_sq2[cc * 64 + l + 32], q1);
            s0 = q0 = s1 = q1 = 0.f; cc = c;
        }
        s0 += n0; q0 += n0 * n0; s1 += n1; q1 += n1 * n1;
    }
    if (uniform) {
        redS[w * 64 + l] = s0;      redQ[w * 64 + l] = q0;
        redS[w * 64 + l + 32] = s1; redQ[w * 64 + l + 32] = q1;
        __syncthreads();
        if (tid < 64) {
            float S = 0.f, Q = 0.f;
#pragma unroll
            for (int r = 0; r < 8; r++) { S += redS[r * 64 + tid]; Q += redQ[r * 64 + tid]; }
            const int c = sC[0];
            atomicAdd(&g_sum2[c * 64 + tid], S);
            atomicAdd(&g_sq2 [c * 64 + tid], Q);
        }
    } else {
        atomicAdd(&g_sum2[cc * 64 + l], s0);      atomicAdd(&g_sq2[cc * 64 + l], q0);
        atomicAdd(&g_sum2[cc * 64 + l + 32], s1); atomicAdd(&g_sq2[cc * 64 + l + 32], q1);
    }
}

// ---------------- kernel 5: norm2 + 2x residual MLP (f32x2) + output ----------------
// dyn smem (ull):
//   pW1 [2][32][34]  pair-interleaved W1^T: (it,p,kp) = (W1[2kp][p], W1[2kp+1][p])
//   pW2 [2][32][32]  (it,p,l) = (W2[p][l], W2[p][l+32])
//   sX  [8w][8e][32] x pairs (x_{2kp}, x_{2kp+1})  (float view: [we][64])
//   sH  [8w][8e][32] duplicated h pairs (h_p, h_p)
#define K5_W1_OFF 0
#define K5_W2_OFF (2 * 32 * 34)
#define K5_X_OFF  (K5_W2_OFF + 2 * 32 * 32)
#define K5_H_OFF  (K5_X_OFF + 8 * 8 * 32)
#define K5_ULL    (K5_H_OFF + 8 * 8 * 32)
#define K5_SMEM   (K5_ULL * 8)

__global__ __launch_bounds__(256) void k_mlp_out(
    const int* __restrict__ ce, const float* __restrict__ edge,
    const float* __restrict__ gamma2, const float* __restrict__ beta2,
    const float* __restrict__ rW1, const float* __restrict__ rB1,
    const float* __restrict__ rW2, const float* __restrict__ rB2,
    float* __restrict__ out)
{
    extern __shared__ ull smu[];
    ull* pW1 = smu + K5_W1_OFF;
    ull* pW2 = smu + K5_W2_OFF;
    ull* sX  = smu + K5_X_OFF;
    ull* sH  = smu + K5_H_OFF;
    __shared__ float sB1[64], sB2[128];
    __shared__ int   sC[NEPB];

    const int tid = threadIdx.x, l = tid & 31, w = tid >> 5;
    const int e0 = blockIdx.x * NEPB;

    // pack W1^T pairs: pW1[it][p][kp] halves (k even -> .x, k odd -> .y)
    {
        float* pf = (float*)pW1;
        for (int idx = tid; idx < 2 * 64 * 32; idx += 256) {
            int it = idx >> 11, k = (idx >> 5) & 63, p = idx & 31;
            pf[(it * 1088 + p * 34 + (k >> 1)) * 2 + (k & 1)] = rW1[idx];
        }
        // pack W2 pairs: pW2[it][p][l] = (W2[p][l], W2[p][l+32])
        float* qf = (float*)pW2;
        for (int idx = tid; idx < 2 * 32 * 64; idx += 256) {
            int it = idx >> 11, p = (idx >> 6) & 31, c = idx & 63;
            qf[(it * 1024 + p * 32 + (c & 31)) * 2 + (c >> 5)] = rW2[idx];
        }
    }
    if (tid < 64)  sB1[tid] = rB1[tid];
    if (tid < 128) sB2[tid] = rB2[tid];
    if (tid < NEPB) sC[tid] = ce[e0 + tid];
    __syncthreads();

    const float ga0 = gamma2[l],      be0 = beta2[l];
    const float ga1 = gamma2[l + 32], be1 = beta2[l + 32];

    // load + norm2; keep x in registers (xa0 = col l, xa1 = col l+32)
    float xa0[8], xa1[8];
#pragma unroll
    for (int i = 0; i < 8; i++) {
        const int e = e0 + w * 8 + i;
        const int c = sC[w * 8 + i];
        float x0 = g_nbr[(size_t)e * 64 + l];
        float x1 = g_nbr[(size_t)e * 64 + l + 32];
        xa0[i] = (x0 - g_mean2[c * 64 + l])      * g_inv2[c * 64 + l]      * ga0 + be0;
        xa1[i] = (x1 - g_mean2[c * 64 + l + 32]) * g_inv2[c * 64 + l + 32] * ga1 + be1;
    }

    float* sXf = (float*)(sX + (size_t)w * 256);   // this warp's 8 edges x 64 floats
    ull*   sHw = sH + (size_t)w * 256;

#pragma unroll
    for (int it = 0; it < 2; it++) {
        // publish x to smem (pairs are naturally contiguous in [e][64] float layout)
#pragma unroll
        for (int i = 0; i < 8; i++) {
            sXf[i * 64 + l]      = xa0[i];
            sXf[i * 64 + l + 32] = xa1[i];
        }
        __syncwarp();

        // ---- h = relu(x @ W1 + B1), thread l owns hidden unit l, 8 edges ----
        ull h[8];
        const ull hinit = f22u(sB1[it * 32 + l], 0.f);
#pragma unroll
        for (int i = 0; i < 8; i++) h[i] = hinit;

        const ull* w1p = pW1 + (size_t)it * 1088 + (size_t)l * 34;
        const ull* xw  = sX + (size_t)w * 256;
#pragma unroll
        for (int kq = 0; kq < 16; kq++) {
            ulonglong2 wv = *(const ulonglong2*)(w1p + 2 * kq);       // LDS128, conflict-free
#pragma unroll
            for (int i = 0; i < 8; i++) {
                ulonglong2 xv = *(const ulonglong2*)(xw + i * 32 + 2 * kq);  // broadcast LDS128
                FMA2(h[i], xv.x, wv.x, h[i]);
                FMA2(h[i], xv.y, wv.y, h[i]);
            }
        }
        // finalize h, duplicate into pairs (h,h) for W2 phase
#pragma unroll
        for (int i = 0; i < 8; i++) {
            float2 hp = u2f2(h[i]);
            float hv = fmaxf(hp.x + hp.y, 0.f);
            sHw[i * 32 + l] = f22u(hv, hv);
        }
        __syncwarp();

        // ---- x += h @ W2 + B2, col-paired acc (x_l, x_{l+32}) ----
        ull acc[8];
        const float b2lo = sB2[it * 64 + l], b2hi = sB2[it * 64 + l + 32];
#pragma unroll
        for (int i = 0; i < 8; i++) acc[i] = f22u(xa0[i] + b2lo, xa1[i] + b2hi);

        const ull* w2p = pW2 + (size_t)it * 1024 + l;
#pragma unroll
        for (int pq = 0; pq < 16; pq++) {
            ull wA = w2p[(2 * pq) * 32];
            ull wB = w2p[(2 * pq + 1) * 32];
#pragma unroll
            for (int i = 0; i < 8; i++) {
                ulonglong2 hv = *(const ulonglong2*)(sHw + i * 32 + 2 * pq);  // broadcast LDS128
                FMA2(acc[i], hv.x, wA, acc[i]);
                FMA2(acc[i], hv.y, wB, acc[i]);
            }
        }
#pragma unroll
        for (int i = 0; i < 8; i++) {
            float2 p = u2f2(acc[i]);
            xa0[i] = p.x; xa1[i] = p.y;
        }
        __syncwarp();
    }

    // out = INV_SQRT2 * relu(edge + x)
#pragma unroll
    for (int i = 0; i < 8; i++) {
        const size_t e = (size_t)(e0 + w * 8 + i);
        float ev0 = edge[e * 64 + l];
        float ev1 = edge[e * 64 + l + 32];
        out[e * 64 + l]      = INV_SQRT2 * fmaxf(ev0 + xa0[i], 0.f);
        out[e * 64 + l + 32] = INV_SQRT2 * fmaxf(ev1 + xa1[i], 0.f);
    }
}

// ---------------- launch ----------------
extern "C" void kernel_launch(void* const* d_in, const int* in_sizes, int n_in,
                              void* d_out, int out_size)
{
    const float* atom   = (const float*)d_in[0];
    const float* edge   = (const float*)d_in[1];
    const int*   nbr    = (const int*)  d_in[2];
    const int*   ce     = (const int*)  d_in[3];
    const float* Wfull  = (const float*)d_in[4];
    const float* Wmask  = (const float*)d_in[5];
    const float* gamma1 = (const float*)d_in[6];
    const float* beta1  = (const float*)d_in[7];
    const float* gamma2 = (const float*)d_in[8];
    const float* beta2  = (const float*)d_in[9];
    const float* rW1    = (const float*)d_in[10];
    const float* rB1    = (const float*)d_in[11];
    const float* rW2    = (const float*)d_in[12];
    const float* rB2    = (const float*)d_in[13];
    float* out = (float*)d_out;

    cudaFuncSetAttribute(k_gemm_stats, cudaFuncAttributeMaxDynamicSharedMemorySize, K1_SMEM);
    cudaFuncSetAttribute(k_mlp_out,    cudaFuncAttributeMaxDynamicSharedMemorySize, K5_SMEM);

    k_zero<<<128, 256>>>();
    k_gemm_stats<<<N_EDGES / NEPB, 256, K1_SMEM>>>(atom, edge, nbr, ce, Wfull);
    k_fin1<<<(NC * 128) / 256, 256>>>();
    k_gate_stats<<<N_EDGES / NEPB, 256>>>(ce, Wmask, gamma1, beta1);
    k_fin2<<<(NC * 64) / 256, 256>>>();
    k_mlp_out<<<N_EDGES / NEPB, 256, K5_SMEM>>>(ce, edge, gamma2, beta2, rW1, rB1, rW2, rB2, out);
}

// round 8
// speedup vs baseline: 1.0052x; 1.0052x over previous
#include <cuda_runtime.h>
#include <math.h>
#include <stddef.h>

#define N_EDGES   1000000
#define FEA       64
#define NC        256
#define NEPB      64
#define EPSV      1e-5f
#define INV_SQRT2 0.70710678118654752f

typedef unsigned long long ull;

// packed fp32x2 FMA (SASS FFMA2) — exact fp32 per lane, 2x FMA throughput
#define FMA2(d, a, b, c) \
    asm("fma.rn.f32x2 %0, %1, %2, %3;" : "=l"(d) : "l"(a), "l"(b), "l"(c))

__device__ __forceinline__ float2 u2f2(ull v) {
    float2 r;
    asm("mov.b64 {%0, %1}, %2;" : "=f"(r.x), "=f"(r.y) : "l"(v));
    return r;
}
__device__ __forceinline__ ull f22u(float lo, float hi) {
    ull r;
    asm("mov.b64 %0, {%1, %2};" : "=l"(r) : "f"(lo), "f"(hi));
    return r;
}

// ---------------- scratch ----------------
__device__ float g_gated[(size_t)N_EDGES * 128];
__device__ float g_nbr[(size_t)N_EDGES * 64];
__device__ float g_sum1[NC * 128];
__device__ float g_sq1 [NC * 128];
__device__ float g_sum2[NC * 64];
__device__ float g_sq2 [NC * 64];
__device__ float g_cnt [NC];
__device__ float g_mean1[NC * 128];
__device__ float g_inv1 [NC * 128];
__device__ float g_mean2[NC * 64];
__device__ float g_inv2 [NC * 64];

// ---------------- kernel 0: zero stats ----------------
__global__ void k_zero() {
    int i = blockIdx.x * blockDim.x + threadIdx.x;
    if (i < NC * 128) { g_sum1[i] = 0.f; g_sq1[i] = 0.f; }
    if (i < NC * 64)  { g_sum2[i] = 0.f; g_sq2[i] = 0.f; }
    if (i < NC)       { g_cnt[i] = 0.f; }
}

// ---------------- kernel 1: gather + GEMM (f32x2 k-paired) + stats1 ----------------
// dyn smem (floats): sA[64][132] | sWT[128][130] (= ull[128][65]) | redS[1024] | redQ[1024]
#define K1_SA    (64 * 132)
#define K1_SWT   (128 * 130)
#define K1_RED   1024
#define K1_SMEM  ((K1_SA + K1_SWT + 2 * K1_RED) * 4)

__global__ __launch_bounds__(256) void k_gemm_stats(
    const float* __restrict__ atom, const float* __restrict__ edge,
    const int* __restrict__ nbr, const int* __restrict__ ce,
    const float* __restrict__ Wfull)
{
    extern __shared__ float sm[];
    float* sA   = sm;                      // [e][k], row stride 132
    float* sWT  = sm + K1_SA;              // transposed W: [j][k], row stride 130 (65 ull, odd -> conflict-free)
    float* redS = sWT + K1_SWT;
    float* redQ = redS + K1_RED;
    __shared__ int sC[NEPB];

    const int tid = threadIdx.x;
    const int e0  = blockIdx.x * NEPB;

    // load W_full transposed: sWT[j][k] = W[k][j]
    for (int idx = tid; idx < 128 * 128; idx += 256) {
        int k = idx >> 7, j = idx & 127;
        sWT[j * 130 + k] = Wfull[idx];
    }

    // load total = [diff | edge] tile
    {
        const int e_l  = tid >> 2;
        const int quad = tid & 3;
        const int eg   = e0 + e_l;
        if (quad == 0) sC[e_l] = ce[eg];
        const int i0 = nbr[2 * eg + 0];
        const int i1 = nbr[2 * eg + 1];
#pragma unroll
        for (int m = 0; m < 4; m++) {
            int k = quad * 16 + m * 4;
            float4 a1 = *(const float4*)(atom + (size_t)i1 * FEA + k);
            float4 a0 = *(const float4*)(atom + (size_t)i0 * FEA + k);
            float4 d;
            d.x = a1.x - a0.x; d.y = a1.y - a0.y; d.z = a1.z - a0.z; d.w = a1.w - a0.w;
            *(float4*)(sA + e_l * 132 + k) = d;
            float4 ev = *(const float4*)(edge + (size_t)eg * FEA + k);
            *(float4*)(sA + e_l * 132 + 64 + k) = ev;
        }
    }
    __syncthreads();

    // GEMM: thread (terow, tcol) computes 8 edges x cols {tcol, tcol+32, tcol+64, tcol+96}
    // k-paired f32x2 accumulators: acc = (sum over even k, sum over odd k)
    const int tcol  = tid & 31;
    const int terow = tid >> 5;

    ull acc[8][4];
#pragma unroll
    for (int i = 0; i < 8; i++)
#pragma unroll
        for (int m = 0; m < 4; m++) acc[i][m] = 0ull;

    const ull* aBase = (const ull*)sA + (size_t)(terow * 8) * 66;   // 132 floats = 66 ull per edge
    const ull* bW    = (const ull*)sWT;                              // 65 ull per j-row
    const ull* b0 = bW + (size_t)tcol * 65;
    const ull* b1 = b0 + (size_t)32 * 65;
    const ull* b2 = b0 + (size_t)64 * 65;
    const ull* b3 = b0 + (size_t)96 * 65;

#pragma unroll 4
    for (int kp = 0; kp < 64; kp++) {
        ull w0 = b0[kp], w1 = b1[kp], w2 = b2[kp], w3 = b3[kp];
#pragma unroll
        for (int i = 0; i < 8; i++) {
            ull a = aBase[i * 66 + kp];   // warp-broadcast LDS64
            FMA2(acc[i][0], a, w0, acc[i][0]);
            FMA2(acc[i][1], a, w1, acc[i][1]);
            FMA2(acc[i][2], a, w2, acc[i][2]);
            FMA2(acc[i][3], a, w3, acc[i][3]);
        }
    }

    // finalize (lo+hi), write gated, compute stats
    float v[8][4];
#pragma unroll
    for (int i = 0; i < 8; i++) {
#pragma unroll
        for (int m = 0; m < 4; m++) {
            float2 p = u2f2(acc[i][m]);
            v[i][m] = p.x + p.y;
        }
        size_t e = (size_t)(e0 + terow * 8 + i);
#pragma unroll
        for (int m = 0; m < 4; m++)
            g_gated[e * 128 + tcol + 32 * m] = v[i][m];
    }

    const int cF = sC[0], cL = sC[NEPB - 1];
    if (cF == cL) {
        float s[4] = {0,0,0,0}, q[4] = {0,0,0,0};
#pragma unroll
        for (int i = 0; i < 8; i++)
#pragma unroll
            for (int m = 0; m < 4; m++) { float x = v[i][m]; s[m] += x; q[m] += x * x; }
#pragma unroll
        for (int m = 0; m < 4; m++) {
            redS[terow * 128 + tcol + 32 * m] = s[m];
            redQ[terow * 128 + tcol + 32 * m] = q[m];
        }
        __syncthreads();
        if (tid < 128) {
            float S = 0.f, Q = 0.f;
#pragma unroll
            for (int r = 0; r < 8; r++) { S += redS[r * 128 + tid]; Q += redQ[r * 128 + tid]; }
            atomicAdd(&g_sum1[cF * 128 + tid], S);
            atomicAdd(&g_sq1 [cF * 128 + tid], Q);
        }
    } else {
        int cc = sC[terow * 8];
        float s[4] = {0,0,0,0}, q[4] = {0,0,0,0};
#pragma unroll
        for (int i = 0; i < 8; i++) {
            int ci = sC[terow * 8 + i];
            if (ci != cc) {
#pragma unroll
                for (int m = 0; m < 4; m++) {
                    int base = cc * 128 + tcol + 32 * m;
                    atomicAdd(&g_sum1[base], s[m]);
                    atomicAdd(&g_sq1 [base], q[m]);
                    s[m] = 0.f; q[m] = 0.f;
                }
                cc = ci;
            }
#pragma unroll
            for (int m = 0; m < 4; m++) { float x = v[i][m]; s[m] += x; q[m] += x * x; }
        }
#pragma unroll
        for (int m = 0; m < 4; m++) {
            int base = cc * 128 + tcol + 32 * m;
            atomicAdd(&g_sum1[base], s[m]);
            atomicAdd(&g_sq1 [base], q[m]);
        }
    }

    if (tid == 0) {
        int cc = sC[0]; float run = 0.f;
        for (int i = 0; i < NEPB; i++) {
            if (sC[i] != cc) { atomicAdd(&g_cnt[cc], run); cc = sC[i]; run = 0.f; }
            run += 1.f;
        }
        atomicAdd(&g_cnt[cc], run);
    }
}

// ---------------- kernel 2/4: finalize stats ----------------
__global__ void k_fin1() {
    int i = blockIdx.x * blockDim.x + threadIdx.x;
    if (i >= NC * 128) return;
    float cnt = fmaxf(g_cnt[i >> 7], 1.f);
    float mean = g_sum1[i] / cnt;
    float var  = g_sq1[i] / cnt - mean * mean;
    g_mean1[i] = mean;
    g_inv1[i]  = rsqrtf(var + EPSV);
}
__global__ void k_fin2() {
    int i = blockIdx.x * blockDim.x + threadIdx.x;
    if (i >= NC * 64) return;
    float cnt = fmaxf(g_cnt[i >> 6], 1.f);
    float mean = g_sum2[i] / cnt;
    float var  = g_sq2[i] / cnt - mean * mean;
    g_mean2[i] = mean;
    g_inv2[i]  = rsqrtf(var + EPSV);
}

// ---------------- kernel 3: norm1 + gate/filter + stats2 (memory-bound, unchanged) ----------------
__global__ __launch_bounds__(256) void k_gate_stats(
    const int* __restrict__ ce, const float* __restrict__ Wmask,
    const float* __restrict__ gamma1, const float* __restrict__ beta1)
{
    __shared__ int   sC[NEPB];
    __shared__ float redS[8 * 64], redQ[8 * 64];
    const int tid = threadIdx.x, l = tid & 31, w = tid >> 5;
    const int e0 = blockIdx.x * NEPB;
    if (tid < NEPB) sC[tid] = ce[e0 + tid];
    __syncthreads();

    const float ga0 = gamma1[l],      be0 = beta1[l];
    const float ga1 = gamma1[l + 32], be1 = beta1[l + 32];
    const float ga2 = gamma1[l + 64], be2 = beta1[l + 64];
    const float ga3 = gamma1[l + 96], be3 = beta1[l + 96];
    const float wm0 = Wmask[l], wm1 = Wmask[l + 32];

    const bool uniform = (sC[0] == sC[NEPB - 1]);
    float s0 = 0.f, q0 = 0.f, s1 = 0.f, q1 = 0.f;
    int cc = sC[w * 8];
#pragma unroll
    for (int i = 0; i < 8; i++) {
        const int e = e0 + w * 8 + i;
        const int c = sC[w * 8 + i];
        const float* gp = g_gated + (size_t)e * 128;
        float x0 = gp[l], x1 = gp[l + 32], x2 = gp[l + 64], x3 = gp[l + 96];
        const float* mp = g_mean1 + c * 128;
        const float* ip = g_inv1  + c * 128;
        x0 = (x0 - mp[l])      * ip[l]      * ga0 + be0;
        x1 = (x1 - mp[l + 32]) * ip[l + 32] * ga1 + be1;
        x2 = (x2 - mp[l + 64]) * ip[l + 64] * ga2 + be2;
        x3 = (x3 - mp[l + 96]) * ip[l + 96] * ga3 + be3;
        float vv = x2 * wm0 + x3 * wm1;
#pragma unroll
        for (int off = 16; off; off >>= 1) vv += __shfl_xor_sync(0xFFFFFFFFu, vv, off);
        float f = tanhf(vv);
        float n0 = f * fmaxf(x0, 0.f);
        float n1 = f * fmaxf(x1, 0.f);
        g_nbr[(size_t)e * 64 + l]      = n0;
        g_nbr[(size_t)e * 64 + l + 32] = n1;
        if (!uniform && c != cc) {
            atomicAdd(&g_sum2[cc * 64 + l], s0);      atomicAdd(&g_sq2[cc * 64 + l], q0);
            atomicAdd(&g_sum2[cc * 64 + l + 32], s1); atomicAdd(&g_sq2[cc * 64 + l + 32], q1);
            s0 = q0 = s1 = q1 = 0.f; cc = c;
        }
        s0 += n0; q0 += n0 * n0; s1 += n1; q1 += n1 * n1;
    }
    if (uniform) {
        redS[w * 64 + l] = s0;      redQ[w * 64 + l] = q0;
        redS[w * 64 + l + 32] = s1; redQ[w * 64 + l + 32] = q1;
        __syncthreads();
        if (tid < 64) {
            float S = 0.f, Q = 0.f;
#pragma unroll
            for (int r = 0; r < 8; r++) { S += redS[r * 64 + tid]; Q += redQ[r * 64 + tid]; }
            const int c = sC[0];
            atomicAdd(&g_sum2[c * 64 + tid], S);
            atomicAdd(&g_sq2 [c * 64 + tid], Q);
        }
    } else {
        atomicAdd(&g_sum2[cc * 64 + l], s0);      atomicAdd(&g_sq2[cc * 64 + l], q0);
        atomicAdd(&g_sum2[cc * 64 + l + 32], s1); atomicAdd(&g_sq2[cc * 64 + l + 32], q1);
    }
}

// ---------------- kernel 5: norm2 + 2x residual MLP (f32x2) + output ----------------
// dyn smem (ull):
//   pW1 [2][32][34]  pair-interleaved W1^T: (it,p,kp) = (W1[2kp][p], W1[2kp+1][p])
//   pW2 [2][32][32]  (it,p,l) = (W2[p][l], W2[p][l+32])
//   sX  [8w][8e][32] x pairs (x_{2kp}, x_{2kp+1})  (float view: [we][64])
//   sH  [8w][8e][32] duplicated h pairs (h_p, h_p)
#define K5_W1_OFF 0
#define K5_W2_OFF (2 * 32 * 34)
#define K5_X_OFF  (K5_W2_OFF + 2 * 32 * 32)
#define K5_H_OFF  (K5_X_OFF + 8 * 8 * 32)
#define K5_ULL    (K5_H_OFF + 8 * 8 * 32)
#define K5_SMEM   (K5_ULL * 8)

__global__ __launch_bounds__(256) void k_mlp_out(
    const int* __restrict__ ce, const float* __restrict__ edge,
    const float* __restrict__ gamma2, const float* __restrict__ beta2,
    const float* __restrict__ rW1, const float* __restrict__ rB1,
    const float* __restrict__ rW2, const float* __restrict__ rB2,
    float* __restrict__ out)
{
    extern __shared__ ull smu[];
    ull* pW1 = smu + K5_W1_OFF;
    ull* pW2 = smu + K5_W2_OFF;
    ull* sX  = smu + K5_X_OFF;
    ull* sH  = smu + K5_H_OFF;
    __shared__ float sB1[64], sB2[128];
    __shared__ int   sC[NEPB];

    const int tid = threadIdx.x, l = tid & 31, w = tid >> 5;
    const int e0 = blockIdx.x * NEPB;

    // pack W1^T pairs: pW1[it][p][kp] halves (k even -> .x, k odd -> .y)
    {
        float* pf = (float*)pW1;
        for (int idx = tid; idx < 2 * 64 * 32; idx += 256) {
            int it = idx >> 11, k = (idx >> 5) & 63, p = idx & 31;
            pf[(it * 1088 + p * 34 + (k >> 1)) * 2 + (k & 1)] = rW1[idx];
        }
        // pack W2 pairs: pW2[it][p][l] = (W2[p][l], W2[p][l+32])
        float* qf = (float*)pW2;
        for (int idx = tid; idx < 2 * 32 * 64; idx += 256) {
            int it = idx >> 11, p = (idx >> 6) & 31, c = idx & 63;
            qf[(it * 1024 + p * 32 + (c & 31)) * 2 + (c >> 5)] = rW2[idx];
        }
    }
    if (tid < 64)  sB1[tid] = rB1[tid];
    if (tid < 128) sB2[tid] = rB2[tid];
    if (tid < NEPB) sC[tid] = ce[e0 + tid];
    __syncthreads();

    const float ga0 = gamma2[l],      be0 = beta2[l];
    const float ga1 = gamma2[l + 32], be1 = beta2[l + 32];

    // load + norm2; keep x in registers (xa0 = col l, xa1 = col l+32)
    float xa0[8], xa1[8];
#pragma unroll
    for (int i = 0; i < 8; i++) {
        const int e = e0 + w * 8 + i;
        const int c = sC[w * 8 + i];
        float x0 = g_nbr[(size_t)e * 64 + l];
        float x1 = g_nbr[(size_t)e * 64 + l + 32];
        xa0[i] = (x0 - g_mean2[c * 64 + l])      * g_inv2[c * 64 + l]      * ga0 + be0;
        xa1[i] = (x1 - g_mean2[c * 64 + l + 32]) * g_inv2[c * 64 + l + 32] * ga1 + be1;
    }

    float* sXf = (float*)(sX + (size_t)w * 256);   // this warp's 8 edges x 64 floats
    ull*   sHw = sH + (size_t)w * 256;

#pragma unroll
    for (int it = 0; it < 2; it++) {
        // publish x to smem (pairs are naturally contiguous in [e][64] float layout)
#pragma unroll
        for (int i = 0; i < 8; i++) {
            sXf[i * 64 + l]      = xa0[i];
            sXf[i * 64 + l + 32] = xa1[i];
        }
        __syncwarp();

        // ---- h = relu(x @ W1 + B1), thread l owns hidden unit l, 8 edges ----
        ull h[8];
        const ull hinit = f22u(sB1[it * 32 + l], 0.f);
#pragma unroll
        for (int i = 0; i < 8; i++) h[i] = hinit;

        const ull* w1p = pW1 + (size_t)it * 1088 + (size_t)l * 34;
        const ull* xw  = sX + (size_t)w * 256;
#pragma unroll
        for (int kq = 0; kq < 16; kq++) {
            ulonglong2 wv = *(const ulonglong2*)(w1p + 2 * kq);       // LDS128, conflict-free
#pragma unroll
            for (int i = 0; i < 8; i++) {
                ulonglong2 xv = *(const ulonglong2*)(xw + i * 32 + 2 * kq);  // broadcast LDS128
                FMA2(h[i], xv.x, wv.x, h[i]);
                FMA2(h[i], xv.y, wv.y, h[i]);
            }
        }
        // finalize h, duplicate into pairs (h,h) for W2 phase
#pragma unroll
        for (int i = 0; i < 8; i++) {
            float2 hp = u2f2(h[i]);
            float hv = fmaxf(hp.x + hp.y, 0.f);
            sHw[i * 32 + l] = f22u(hv, hv);
        }
        __syncwarp();

        // ---- x += h @ W2 + B2, col-paired acc (x_l, x_{l+32}) ----
        ull acc[8];
        const float b2lo = sB2[it * 64 + l], b2hi = sB2[it * 64 + l + 32];
#pragma unroll
        for (int i = 0; i < 8; i++) acc[i] = f22u(xa0[i] + b2lo, xa1[i] + b2hi);

        const ull* w2p = pW2 + (size_t)it * 1024 + l;
#pragma unroll
        for (int pq = 0; pq < 16; pq++) {
            ull wA = w2p[(2 * pq) * 32];
            ull wB = w2p[(2 * pq + 1) * 32];
#pragma unroll
            for (int i = 0; i < 8; i++) {
                ulonglong2 hv = *(const ulonglong2*)(sHw + i * 32 + 2 * pq);  // broadcast LDS128
                FMA2(acc[i], hv.x, wA, acc[i]);
                FMA2(acc[i], hv.y, wB, acc[i]);
            }
        }
#pragma unroll
        for (int i = 0; i < 8; i++) {
            float2 p = u2f2(acc[i]);
            xa0[i] = p.x; xa1[i] = p.y;
        }
        __syncwarp();
    }

    // out = INV_SQRT2 * relu(edge + x)
#pragma unroll
    for (int i = 0; i < 8; i++) {
        const size_t e = (size_t)(e0 + w * 8 + i);
        float ev0 = edge[e * 64 + l];
        float ev1 = edge[e * 64 + l + 32];
        out[e * 64 + l]      = INV_SQRT2 * fmaxf(ev0 + xa0[i], 0.f);
        out[e * 64 + l + 32] = INV_SQRT2 * fmaxf(ev1 + xa1[i], 0.f);
    }
}

// ---------------- launch ----------------
extern "C" void kernel_launch(void* const* d_in, const int* in_sizes, int n_in,
                              void* d_out, int out_size)
{
    const float* atom   = (const float*)d_in[0];
    const float* edge   = (const float*)d_in[1];
    const int*   nbr    = (const int*)  d_in[2];
    const int*   ce     = (const int*)  d_in[3];
    const float* Wfull  = (const float*)d_in[4];
    const float* Wmask  = (const float*)d_in[5];
    const float* gamma1 = (const float*)d_in[6];
    const float* beta1  = (const float*)d_in[7];
    const float* gamma2 = (const float*)d_in[8];
    const float* beta2  = (const float*)d_in[9];
    const float* rW1    = (const float*)d_in[10];
    const float* rB1    = (const float*)d_in[11];
    const float* rW2    = (const float*)d_in[12];
    const float* rB2    = (const float*)d_in[13];
    float* out = (float*)d_out;

    cudaFuncSetAttribute(k_gemm_stats, cudaFuncAttributeMaxDynamicSharedMemorySize, K1_SMEM);
    cudaFuncSetAttribute(k_mlp_out,    cudaFuncAttributeMaxDynamicSharedMemorySize, K5_SMEM);

    k_zero<<<128, 256>>>();
    k_gemm_stats<<<N_EDGES / NEPB, 256, K1_SMEM>>>(atom, edge, nbr, ce, Wfull);
    k_fin1<<<(NC * 128) / 256, 256>>>();
    k_gate_stats<<<N_EDGES / NEPB, 256>>>(ce, Wmask, gamma1, beta1);
    k_fin2<<<(NC * 64) / 256, 256>>>();
    k_mlp_out<<<N_EDGES / NEPB, 256, K5_SMEM>>>(ce, edge, gamma2, beta2, rW1, rB1, rW2, rB2, out);
}

// round 9
// speedup vs baseline: 1.0071x; 1.0018x over previous
#include <cuda_runtime.h>
#include <math.h>
#include <stddef.h>

#define N_EDGES   1000000
#define FEA       64
#define NC        256
#define NEPB      64
#define EPSV      1e-5f
#define INV_SQRT2 0.70710678118654752f

typedef unsigned long long ull;

// packed fp32x2 FMA (SASS FFMA2) — exact fp32 per lane, 2x FMA throughput
#define FMA2(d, a, b, c) \
    asm("fma.rn.f32x2 %0, %1, %2, %3;" : "=l"(d) : "l"(a), "l"(b), "l"(c))

__device__ __forceinline__ float2 u2f2(ull v) {
    float2 r;
    asm("mov.b64 {%0, %1}, %2;" : "=f"(r.x), "=f"(r.y) : "l"(v));
    return r;
}
__device__ __forceinline__ ull f22u(float lo, float hi) {
    ull r;
    asm("mov.b64 %0, {%1, %2};" : "=l"(r) : "f"(lo), "f"(hi));
    return r;
}

// ---------------- scratch ----------------
__device__ float g_gated[(size_t)N_EDGES * 128];
__device__ float g_nbr[(size_t)N_EDGES * 64];
__device__ float g_sum1[NC * 128];
__device__ float g_sq1 [NC * 128];
__device__ float g_sum2[NC * 64];
__device__ float g_sq2 [NC * 64];
__device__ float g_cnt [NC];
__device__ float g_mean1[NC * 128];
__device__ float g_inv1 [NC * 128];
__device__ float g_mean2[NC * 64];
__device__ float g_inv2 [NC * 64];

// ---------------- kernel 0: zero stats ----------------
__global__ void k_zero() {
    int i = blockIdx.x * blockDim.x + threadIdx.x;
    if (i < NC * 128) { g_sum1[i] = 0.f; g_sq1[i] = 0.f; }
    if (i < NC * 64)  { g_sum2[i] = 0.f; g_sq2[i] = 0.f; }
    if (i < NC)       { g_cnt[i] = 0.f; }
}

// ---------------- kernel 1: gather + GEMM (f32x2 k-paired) + stats1 ----------------
// dyn smem (floats): sA[64][132] | sWT[128][130] (= ull[128][65]) | redS[1024] | redQ[1024]
#define K1_SA    (64 * 132)
#define K1_SWT   (128 * 130)
#define K1_RED   1024
#define K1_SMEM  ((K1_SA + K1_SWT + 2 * K1_RED) * 4)

__global__ __launch_bounds__(256) void k_gemm_stats(
    const float* __restrict__ atom, const float* __restrict__ edge,
    const int* __restrict__ nbr, const int* __restrict__ ce,
    const float* __restrict__ Wfull)
{
    extern __shared__ float sm[];
    float* sA   = sm;                      // [e][k], row stride 132
    float* sWT  = sm + K1_SA;              // transposed W: [j][k], row stride 130 (65 ull, odd -> conflict-free)
    float* redS = sWT + K1_SWT;
    float* redQ = redS + K1_RED;
    __shared__ int sC[NEPB];

    const int tid = threadIdx.x;
    const int e0  = blockIdx.x * NEPB;

    // load W_full transposed: sWT[j][k] = W[k][j]
    for (int idx = tid; idx < 128 * 128; idx += 256) {
        int k = idx >> 7, j = idx & 127;
        sWT[j * 130 + k] = Wfull[idx];
    }

    // load total = [diff | edge] tile
    {
        const int e_l  = tid >> 2;
        const int quad = tid & 3;
        const int eg   = e0 + e_l;
        if (quad == 0) sC[e_l] = ce[eg];
        const int i0 = nbr[2 * eg + 0];
        const int i1 = nbr[2 * eg + 1];
#pragma unroll
        for (int m = 0; m < 4; m++) {
            int k = quad * 16 + m * 4;
            float4 a1 = *(const float4*)(atom + (size_t)i1 * FEA + k);
            float4 a0 = *(const float4*)(atom + (size_t)i0 * FEA + k);
            float4 d;
            d.x = a1.x - a0.x; d.y = a1.y - a0.y; d.z = a1.z - a0.z; d.w = a1.w - a0.w;
            *(float4*)(sA + e_l * 132 + k) = d;
            float4 ev = *(const float4*)(edge + (size_t)eg * FEA + k);
            *(float4*)(sA + e_l * 132 + 64 + k) = ev;
        }
    }
    __syncthreads();

    // GEMM: thread (terow, tcol) computes 8 edges x cols {tcol, tcol+32, tcol+64, tcol+96}
    // k-paired f32x2 accumulators: acc = (sum over even k, sum over odd k)
    const int tcol  = tid & 31;
    const int terow = tid >> 5;

    ull acc[8][4];
#pragma unroll
    for (int i = 0; i < 8; i++)
#pragma unroll
        for (int m = 0; m < 4; m++) acc[i][m] = 0ull;

    const ull* aBase = (const ull*)sA + (size_t)(terow * 8) * 66;   // 132 floats = 66 ull per edge
    const ull* bW    = (const ull*)sWT;                              // 65 ull per j-row
    const ull* b0 = bW + (size_t)tcol * 65;
    const ull* b1 = b0 + (size_t)32 * 65;
    const ull* b2 = b0 + (size_t)64 * 65;
    const ull* b3 = b0 + (size_t)96 * 65;

#pragma unroll 4
    for (int kp = 0; kp < 64; kp++) {
        ull w0 = b0[kp], w1 = b1[kp], w2 = b2[kp], w3 = b3[kp];
#pragma unroll
        for (int i = 0; i < 8; i++) {
            ull a = aBase[i * 66 + kp];   // warp-broadcast LDS64
            FMA2(acc[i][0], a, w0, acc[i][0]);
            FMA2(acc[i][1], a, w1, acc[i][1]);
            FMA2(acc[i][2], a, w2, acc[i][2]);
            FMA2(acc[i][3], a, w3, acc[i][3]);
        }
    }

    // finalize (lo+hi), write gated, compute stats
    float v[8][4];
#pragma unroll
    for (int i = 0; i < 8; i++) {
#pragma unroll
        for (int m = 0; m < 4; m++) {
            float2 p = u2f2(acc[i][m]);
            v[i][m] = p.x + p.y;
        }
        size_t e = (size_t)(e0 + terow * 8 + i);
#pragma unroll
        for (int m = 0; m < 4; m++)
            g_gated[e * 128 + tcol + 32 * m] = v[i][m];
    }

    const int cF = sC[0], cL = sC[NEPB - 1];
    if (cF == cL) {
        float s[4] = {0,0,0,0}, q[4] = {0,0,0,0};
#pragma unroll
        for (int i = 0; i < 8; i++)
#pragma unroll
            for (int m = 0; m < 4; m++) { float x = v[i][m]; s[m] += x; q[m] += x * x; }
#pragma unroll
        for (int m = 0; m < 4; m++) {
            redS[terow * 128 + tcol + 32 * m] = s[m];
            redQ[terow * 128 + tcol + 32 * m] = q[m];
        }
        __syncthreads();
        if (tid < 128) {
            float S = 0.f, Q = 0.f;
#pragma unroll
            for (int r = 0; r < 8; r++) { S += redS[r * 128 + tid]; Q += redQ[r * 128 + tid]; }
            atomicAdd(&g_sum1[cF * 128 + tid], S);
            atomicAdd(&g_sq1 [cF * 128 + tid], Q);
        }
    } else {
        int cc = sC[terow * 8];
        float s[4] = {0,0,0,0}, q[4] = {0,0,0,0};
#pragma unroll
        for (int i = 0; i < 8; i++) {
            int ci = sC[terow * 8 + i];
            if (ci != cc) {
#pragma unroll
                for (int m = 0; m < 4; m++) {
                    int base = cc * 128 + tcol + 32 * m;
                    atomicAdd(&g_sum1[base], s[m]);
                    atomicAdd(&g_sq1 [base], q[m]);
                    s[m] = 0.f; q[m] = 0.f;
                }
                cc = ci;
            }
#pragma unroll
            for (int m = 0; m < 4; m++) { float x = v[i][m]; s[m] += x; q[m] += x * x; }
        }
#pragma unroll
        for (int m = 0; m < 4; m++) {
            int base = cc * 128 + tcol + 32 * m;
            atomicAdd(&g_sum1[base], s[m]);
            atomicAdd(&g_sq1 [base], q[m]);
        }
    }

    if (tid == 0) {
        int cc = sC[0]; float run = 0.f;
        for (int i = 0; i < NEPB; i++) {
            if (sC[i] != cc) { atomicAdd(&g_cnt[cc], run); cc = sC[i]; run = 0.f; }
            run += 1.f;
        }
        atomicAdd(&g_cnt[cc], run);
    }
}

// ---------------- kernel 2/4: finalize stats ----------------
__global__ void k_fin1() {
    int i = blockIdx.x * blockDim.x + threadIdx.x;
    if (i >= NC * 128) return;
    float cnt = fmaxf(g_cnt[i >> 7], 1.f);
    float mean = g_sum1[i] / cnt;
    float var  = g_sq1[i] / cnt - mean * mean;
    g_mean1[i] = mean;
    g_inv1[i]  = rsqrtf(var + EPSV);
}
__global__ void k_fin2() {
    int i = blockIdx.x * blockDim.x + threadIdx.x;
    if (i >= NC * 64) return;
    float cnt = fmaxf(g_cnt[i >> 6], 1.f);
    float mean = g_sum2[i] / cnt;
    float var  = g_sq2[i] / cnt - mean * mean;
    g_mean2[i] = mean;
    g_inv2[i]  = rsqrtf(var + EPSV);
}

// ---------------- kernel 3: norm1 + gate/filter + stats2 (memory-bound, unchanged) ----------------
__global__ __launch_bounds__(256) void k_gate_stats(
    const int* __restrict__ ce, const float* __restrict__ Wmask,
    const float* __restrict__ gamma1, const float* __restrict__ beta1)
{
    __shared__ int   sC[NEPB];
    __shared__ float redS[8 * 64], redQ[8 * 64];
    const int tid = threadIdx.x, l = tid & 31, w = tid >> 5;
    const int e0 = blockIdx.x * NEPB;
    if (tid < NEPB) sC[tid] = ce[e0 + tid];
    __syncthreads();

    const float ga0 = gamma1[l],      be0 = beta1[l];
    const float ga1 = gamma1[l + 32], be1 = beta1[l + 32];
    const float ga2 = gamma1[l + 64], be2 = beta1[l + 64];
    const float ga3 = gamma1[l + 96], be3 = beta1[l + 96];
    const float wm0 = Wmask[l], wm1 = Wmask[l + 32];

    const bool uniform = (sC[0] == sC[NEPB - 1]);
    float s0 = 0.f, q0 = 0.f, s1 = 0.f, q1 = 0.f;
    int cc = sC[w * 8];
#pragma unroll
    for (int i = 0; i < 8; i++) {
        const int e = e0 + w * 8 + i;
        const int c = sC[w * 8 + i];
        const float* gp = g_gated + (size_t)e * 128;
        float x0 = gp[l], x1 = gp[l + 32], x2 = gp[l + 64], x3 = gp[l + 96];
        const float* mp = g_mean1 + c * 128;
        const float* ip = g_inv1  + c * 128;
        x0 = (x0 - mp[l])      * ip[l]      * ga0 + be0;
        x1 = (x1 - mp[l + 32]) * ip[l + 32] * ga1 + be1;
        x2 = (x2 - mp[l + 64]) * ip[l + 64] * ga2 + be2;
        x3 = (x3 - mp[l + 96]) * ip[l + 96] * ga3 + be3;
        float vv = x2 * wm0 + x3 * wm1;
#pragma unroll
        for (int off = 16; off; off >>= 1) vv += __shfl_xor_sync(0xFFFFFFFFu, vv, off);
        float f = tanhf(vv);
        float n0 = f * fmaxf(x0, 0.f);
        float n1 = f * fmaxf(x1, 0.f);
        g_nbr[(size_t)e * 64 + l]      = n0;
        g_nbr[(size_t)e * 64 + l + 32] = n1;
        if (!uniform && c != cc) {
            atomicAdd(&g_sum2[cc * 64 + l], s0);      atomicAdd(&g_sq2[cc * 64 + l], q0);
            atomicAdd(&g_sum2[cc * 64 + l + 32], s1); atomicAdd(&g_sq2[cc * 64 + l + 32], q1);
            s0 = q0 = s1 = q1 = 0.f; cc = c;
        }
        s0 += n0; q0 += n0 * n0; s1 += n1; q1 += n1 * n1;
    }
    if (uniform) {
        redS[w * 64 + l] = s0;      redQ[w * 64 + l] = q0;
        redS[w * 64 + l + 32] = s1; redQ[w * 64 + l + 32] = q1;
        __syncthreads();
        if (tid < 64) {
            float S = 0.f, Q = 0.f;
#pragma unroll
            for (int r = 0; r < 8; r++) { S += redS[r * 64 + tid]; Q += redQ[r * 64 + tid]; }
            const int c = sC[0];
            atomicAdd(&g_sum2[c * 64 + tid], S);
            atomicAdd(&g_sq2 [c * 64 + tid], Q);
        }
    } else {
        atomicAdd(&g_sum2[cc * 64 + l], s0);      atomicAdd(&g_sq2[cc * 64 + l], q0);
        atomicAdd(&g_sum2[cc * 64 + l + 32], s1); atomicAdd(&g_sq2[cc * 64 + l + 32], q1);
    }
}

// ---------------- kernel 5: norm2 + 2x residual MLP (f32x2) + output ----------------
// dyn smem (ull):
//   pW1 [2][32][34]  pair-interleaved W1^T: (it,p,kp) = (W1[2kp][p], W1[2kp+1][p])
//   pW2 [2][32][32]  (it,p,l) = (W2[p][l], W2[p][l+32])
//   sX  [8w][8e][32] x pairs (x_{2kp}, x_{2kp+1})  (float view: [we][64])
//   sH  [8w][8e][32] duplicated h pairs (h_p, h_p)
#define K5_W1_OFF 0
#define K5_W2_OFF (2 * 32 * 34)
#define K5_X_OFF  (K5_W2_OFF + 2 * 32 * 32)
#define K5_H_OFF  (K5_X_OFF + 8 * 8 * 32)
#define K5_ULL    (K5_H_OFF + 8 * 8 * 32)
#define K5_SMEM   (K5_ULL * 8)

__global__ __launch_bounds__(256) void k_mlp_out(
    const int* __restrict__ ce, const float* __restrict__ edge,
    const float* __restrict__ gamma2, const float* __restrict__ beta2,
    const float* __restrict__ rW1, const float* __restrict__ rB1,
    const float* __restrict__ rW2, const float* __restrict__ rB2,
    float* __restrict__ out)
{
    extern __shared__ ull smu[];
    ull* pW1 = smu + K5_W1_OFF;
    ull* pW2 = smu + K5_W2_OFF;
    ull* sX  = smu + K5_X_OFF;
    ull* sH  = smu + K5_H_OFF;
    __shared__ float sB1[64], sB2[128];
    __shared__ int   sC[NEPB];

    const int tid = threadIdx.x, l = tid & 31, w = tid >> 5;
    const int e0 = blockIdx.x * NEPB;

    // pack W1^T pairs: pW1[it][p][kp] halves (k even -> .x, k odd -> .y)
    {
        float* pf = (float*)pW1;
        for (int idx = tid; idx < 2 * 64 * 32; idx += 256) {
            int it = idx >> 11, k = (idx >> 5) & 63, p = idx & 31;
            pf[(it * 1088 + p * 34 + (k >> 1)) * 2 + (k & 1)] = rW1[idx];
        }
        // pack W2 pairs: pW2[it][p][l] = (W2[p][l], W2[p][l+32])
        float* qf = (float*)pW2;
        for (int idx = tid; idx < 2 * 32 * 64; idx += 256) {
            int it = idx >> 11, p = (idx >> 6) & 31, c = idx & 63;
            qf[(it * 1024 + p * 32 + (c & 31)) * 2 + (c >> 5)] = rW2[idx];
        }
    }
    if (tid < 64)  sB1[tid] = rB1[tid];
    if (tid < 128) sB2[tid] = rB2[tid];
    if (tid < NEPB) sC[tid] = ce[e0 + tid];
    __syncthreads();

    const float ga0 = gamma2[l],      be0 = beta2[l];
    const float ga1 = gamma2[l + 32], be1 = beta2[l + 32];

    // load + norm2; keep x in registers (xa0 = col l, xa1 = col l+32)
    float xa0[8], xa1[8];
#pragma unroll
    for (int i = 0; i < 8; i++) {
        const int e = e0 + w * 8 + i;
        const int c = sC[w * 8 + i];
        float x0 = g_nbr[(size_t)e * 64 + l];
        float x1 = g_nbr[(size_t)e * 64 + l + 32];
        xa0[i] = (x0 - g_mean2[c * 64 + l])      * g_inv2[c * 64 + l]      * ga0 + be0;
        xa1[i] = (x1 - g_mean2[c * 64 + l + 32]) * g_inv2[c * 64 + l + 32] * ga1 + be1;
    }

    float* sXf = (float*)(sX + (size_t)w * 256);   // this warp's 8 edges x 64 floats
    ull*   sHw = sH + (size_t)w * 256;

#pragma unroll
    for (int it = 0; it < 2; it++) {
        // publish x to smem (pairs are naturally contiguous in [e][64] float layout)
#pragma unroll
        for (int i = 0; i < 8; i++) {
            sXf[i * 64 + l]      = xa0[i];
            sXf[i * 64 + l + 32] = xa1[i];
        }
        __syncwarp();

        // ---- h = relu(x @ W1 + B1), thread l owns hidden unit l, 8 edges ----
        ull h[8];
        const ull hinit = f22u(sB1[it * 32 + l], 0.f);
#pragma unroll
        for (int i = 0; i < 8; i++) h[i] = hinit;

        const ull* w1p = pW1 + (size_t)it * 1088 + (size_t)l * 34;
        const ull* xw  = sX + (size_t)w * 256;
#pragma unroll
        for (int kq = 0; kq < 16; kq++) {
            ulonglong2 wv = *(const ulonglong2*)(w1p + 2 * kq);       // LDS128, conflict-free
#pragma unroll
            for (int i = 0; i < 8; i++) {
                ulonglong2 xv = *(const ulonglong2*)(xw + i * 32 + 2 * kq);  // broadcast LDS128
                FMA2(h[i], xv.x, wv.x, h[i]);
                FMA2(h[i], xv.y, wv.y, h[i]);
            }
        }
        // finalize h, duplicate into pairs (h,h) for W2 phase
#pragma unroll
        for (int i = 0; i < 8; i++) {
            float2 hp = u2f2(h[i]);
            float hv = fmaxf(hp.x + hp.y, 0.f);
            sHw[i * 32 + l] = f22u(hv, hv);
        }
        __syncwarp();

        // ---- x += h @ W2 + B2, col-paired acc (x_l, x_{l+32}) ----
        ull acc[8];
        const float b2lo = sB2[it * 64 + l], b2hi = sB2[it * 64 + l + 32];
#pragma unroll
        for (int i = 0; i < 8; i++) acc[i] = f22u(xa0[i] + b2lo, xa1[i] + b2hi);

        const ull* w2p = pW2 + (size_t)it * 1024 + l;
#pragma unroll
        for (int pq = 0; pq < 16; pq++) {
            ull wA = w2p[(2 * pq) * 32];
            ull wB = w2p[(2 * pq + 1) * 32];
#pragma unroll
            for (int i = 0; i < 8; i++) {
                ulonglong2 hv = *(const ulonglong2*)(sHw + i * 32 + 2 * pq);  // broadcast LDS128
                FMA2(acc[i], hv.x, wA, acc[i]);
                FMA2(acc[i], hv.y, wB, acc[i]);
            }
        }
#pragma unroll
        for (int i = 0; i < 8; i++) {
            float2 p = u2f2(acc[i]);
            xa0[i] = p.x; xa1[i] = p.y;
        }
        __syncwarp();
    }

    // out = INV_SQRT2 * relu(edge + x)
#pragma unroll
    for (int i = 0; i < 8; i++) {
        const size_t e = (size_t)(e0 + w * 8 + i);
        float ev0 = edge[e * 64 + l];
        float ev1 = edge[e * 64 + l + 32];
        out[e * 64 + l]      = INV_SQRT2 * fmaxf(ev0 + xa0[i], 0.f);
        out[e * 64 + l + 32] = INV_SQRT2 * fmaxf(ev1 + xa1[i], 0.f);
    }
}

// ---------------- launch ----------------
extern "C" void kernel_launch(void* const* d_in, const int* in_sizes, int n_in,
                              void* d_out, int out_size)
{
    const float* atom   = (const float*)d_in[0];
    const float* edge   = (const float*)d_in[1];
    const int*   nbr    = (const int*)  d_in[2];
    const int*   ce     = (const int*)  d_in[3];
    const float* Wfull  = (const float*)d_in[4];
    const float* Wmask  = (const float*)d_in[5];
    const float* gamma1 = (const float*)d_in[6];
    const float* beta1  = (const float*)d_in[7];
    const float* gamma2 = (const float*)d_in[8];
    const float* beta2  = (const float*)d_in[9];
    const float* rW1    = (const float*)d_in[10];
    const float* rB1    = (const float*)d_in[11];
    const float* rW2    = (const float*)d_in[12];
    const float* rB2    = (const float*)d_in[13];
    float* out = (float*)d_out;

    cudaFuncSetAttribute(k_gemm_stats, cudaFuncAttributeMaxDynamicSharedMemorySize, K1_SMEM);
    cudaFuncSetAttribute(k_mlp_out,    cudaFuncAttributeMaxDynamicSharedMemorySize, K5_SMEM);

    k_zero<<<128, 256>>>();
    k_gemm_stats<<<N_EDGES / NEPB, 256, K1_SMEM>>>(atom, edge, nbr, ce, Wfull);
    k_fin1<<<(NC * 128) / 256, 256>>>();
    k_gate_stats<<<N_EDGES / NEPB, 256>>>(ce, Wmask, gamma1, beta1);
    k_fin2<<<(NC * 64) / 256, 256>>>();
    k_mlp_out<<<N_EDGES / NEPB, 256, K5_SMEM>>>(ce, edge, gamma2, beta2, rW1, rB1, rW2, rB2, out);
}